// round 13
// baseline (speedup 1.0000x reference)
#include <cuda_runtime.h>
#include <cuda_bf16.h>
#include <cuda_fp16.h>
#include <cstdint>

// Problem constants (fixed by the dataset)
#define NN   20000
#define EE   160000
#define HID  128
#define NHEADS 4
#define GG   64
#define NCC  8
#define HC   512
#define MPK  2560      // packed projection width: [skip | q | k | v | ts]
#define KVW  1536      // fp16 side-band width: [q(512) | (k128,v128) x 4 heads]
#define NEGBIG (-1.0e30f)

// ---------------------------------------------------------------------------
// Scratch (device globals: allocation-free contract)
// ---------------------------------------------------------------------------
__device__ float  g_agg [NN * HID];
__device__ float  g_h   [NN * HID];
__device__ float  g_h3  [NN * HID];
__device__ float  g_h4  [NN * HID];
__device__ float  g_h5  [NN * HID];
__device__ __half g_x16 [NN * HID];           // fp16 mirror of input x
__device__ __half g_h316[NN * HID];           // fp16 mirror of h3
__device__ __half g_h416[NN * HID];           // fp16 mirror of h4
__device__ float  g_pack[(size_t)NN * MPK];   // fp32: skip + ts slots used
__device__ __half g_kvq [(size_t)NN * KVW];   // fp16: q,k,v compact
__device__ float  g_h2  [NN * HC];
__device__ float  g_Wpk [HID * MPK];
__device__ float  g_bpk [MPK];
__device__ float  g_pool[GG * HID];
__device__ float  g_cnt [GG];
// CSR (by dst)
__device__ int    g_deg [NN];
__device__ int    g_cur [NN];
__device__ int    g_off [NN + 1];
__device__ int    g_srcs[EE];

// ---------------------------------------------------------------------------
// mma.sync fp16 GEMM (single MMA, f32 accumulate) + register-prefetch pipeline
// C[Nrows, Mtot] = op( A@W [+ A2@W2] [+bias] [+add1] ), W: [K, Mtot]
// Optional: cols [512,2048) diverted to fp16 side-band C16 (q/k/v layout).
// Optional: full-width fp16 mirror Cmir (post-relu copy of C).
// CTA tile 128x64, BK=32. 8 warps (2m x 4n), warp tile 64x16, 2 CTAs/SM.
// ---------------------------------------------------------------------------
#define A_T  0
#define B_T  10240
#define SSTR 80

__device__ __forceinline__ unsigned pack_h16(float x, float y) {
    __half2 p = __float22half2_rn(make_float2(x, y));
    return *(unsigned*)&p;
}

__device__ __forceinline__ void mma_f16(float* c, const unsigned* a, const unsigned* b) {
    asm volatile(
        "mma.sync.aligned.m16n8k16.row.col.f32.f16.f16.f32 "
        "{%0,%1,%2,%3}, {%4,%5,%6,%7}, {%8,%9}, {%0,%1,%2,%3};"
        : "+f"(c[0]), "+f"(c[1]), "+f"(c[2]), "+f"(c[3])
        : "r"(a[0]), "r"(a[1]), "r"(a[2]), "r"(a[3]), "r"(b[0]), "r"(b[1]));
}

__device__ __forceinline__ void load_tiles(const float* __restrict__ Ap,
                                           const float* __restrict__ Wp,
                                           int K, int Mtot, int Nrows,
                                           int brow, int bcol, int k0, int tid,
                                           float4 pa[4], float4 pb[2])
{
#pragma unroll
    for (int t = 0; t < 4; ++t) {
        int idx = tid + t * 256;
        int r   = idx >> 3;
        int kg  = idx & 7;
        pa[t] = make_float4(0.f, 0.f, 0.f, 0.f);
        if (brow + r < Nrows)
            pa[t] = *(const float4*)(Ap + (size_t)(brow + r) * K + k0 + kg * 4);
    }
#pragma unroll
    for (int t = 0; t < 2; ++t) {
        int idx = tid + t * 256;
        int n   = idx & 63;
        int kg  = idx >> 6;
        const float* wp = Wp + (size_t)(k0 + kg * 4) * Mtot + bcol + n;
        pb[t] = make_float4(wp[0], wp[Mtot], wp[2 * (size_t)Mtot],
                            wp[3 * (size_t)Mtot]);
    }
}

__global__ void __launch_bounds__(256, 2)
gemm_mma(const float* __restrict__ A,  const float* __restrict__ W,
         const float* __restrict__ A2, const float* __restrict__ W2,
         const float* __restrict__ bias,
         const float* __restrict__ add1,
         float* __restrict__ C, __half* __restrict__ C16,
         __half* __restrict__ Cmir,
         int Nrows, int K, int Mtot, int do_relu)
{
    __shared__ __align__(16) char smem[15360];

    const int tid    = threadIdx.x;
    const int wid    = tid >> 5;
    const int lane   = tid & 31;
    const int warp_m = wid >> 2;
    const int warp_n = wid & 3;
    const int g      = lane >> 2;
    const int t4     = (lane & 3) * 4;
    const int brow   = blockIdx.x * 128;
    const int bcol   = blockIdx.y * 64;

    float acc[4][2][4];
#pragma unroll
    for (int i = 0; i < 4; i++)
#pragma unroll
        for (int j = 0; j < 2; j++)
#pragma unroll
            for (int r = 0; r < 4; r++) acc[i][j][r] = 0.f;

    const int kch = K >> 5;
    const int nch = A2 ? kch * 2 : kch;

    float4 pa[4], pb[2];
    load_tiles(A, W, K, Mtot, Nrows, brow, bcol, 0, tid, pa, pb);

    for (int c = 0; c < nch; ++c) {
        __syncthreads();   // previous compute done; smem free

        // ---- store prefetched regs -> smem (convert fp32 -> fp16)
#pragma unroll
        for (int t = 0; t < 4; ++t) {
            int idx = tid + t * 256;
            int r   = idx >> 3;
            int kg  = idx & 7;
            *(uint2*)(smem + A_T + r * SSTR + kg * 8) =
                make_uint2(pack_h16(pa[t].x, pa[t].y), pack_h16(pa[t].z, pa[t].w));
        }
#pragma unroll
        for (int t = 0; t < 2; ++t) {
            int idx = tid + t * 256;
            int n   = idx & 63;
            int kg  = idx >> 6;
            *(uint2*)(smem + B_T + n * SSTR + kg * 8) =
                make_uint2(pack_h16(pb[t].x, pb[t].y), pack_h16(pb[t].z, pb[t].w));
        }

        // ---- issue next chunk's global loads (overlap with MMA below)
        if (c + 1 < nch) {
            int cn   = c + 1;
            int pass = cn / kch;
            int k0   = (cn % kch) * 32;
            load_tiles(pass ? A2 : A, pass ? W2 : W, K, Mtot, Nrows,
                       brow, bcol, k0, tid, pa, pb);
        }
        __syncthreads();   // smem tiles ready

        // ---- compute: 2 k-steps of 16
#pragma unroll
        for (int ks = 0; ks < 2; ++ks) {
            const int ko = ks * 32;
            unsigned aF[4][4], bF[2][2];
#pragma unroll
            for (int nt = 0; nt < 2; ++nt) {
                int nb = (warp_n * 16 + nt * 8 + g) * SSTR + t4 + ko;
                bF[nt][0] = *(const unsigned*)(smem + B_T + nb);
                bF[nt][1] = *(const unsigned*)(smem + B_T + nb + 16);
            }
#pragma unroll
            for (int mt = 0; mt < 4; ++mt) {
                int mb = (warp_m * 64 + mt * 16 + g) * SSTR + t4 + ko;
                aF[mt][0] = *(const unsigned*)(smem + A_T + mb);
                aF[mt][1] = *(const unsigned*)(smem + A_T + mb + 8 * SSTR);
                aF[mt][2] = *(const unsigned*)(smem + A_T + mb + 16);
                aF[mt][3] = *(const unsigned*)(smem + A_T + mb + 8 * SSTR + 16);
            }
#pragma unroll
            for (int mt = 0; mt < 4; ++mt)
#pragma unroll
                for (int nt = 0; nt < 2; ++nt)
                    mma_f16(acc[mt][nt], aF[mt], bF[nt]);
        }
    }

    // ---- epilogue
#pragma unroll
    for (int mt = 0; mt < 4; ++mt) {
#pragma unroll
        for (int nt = 0; nt < 2; ++nt) {
            int col = bcol + warp_n * 16 + nt * 8 + (lane & 3) * 2;
#pragma unroll
            for (int half = 0; half < 2; ++half) {
                int row = brow + warp_m * 64 + mt * 16 + g + half * 8;
                if (row >= Nrows) continue;
                float v0 = acc[mt][nt][half * 2 + 0];
                float v1 = acc[mt][nt][half * 2 + 1];
                if (bias) {
                    float2 b = *(const float2*)(bias + col);
                    v0 += b.x; v1 += b.y;
                }
                // fp16 side-band for q/k/v columns
                if (C16) {
                    int cg = col - 512;
                    if (cg >= 0 && cg < 1536) {
                        int hoff;
                        if (cg < 512) {
                            hoff = cg;                                    // q
                        } else if (cg < 1024) {
                            int t2 = cg - 512;                            // k
                            hoff = 512 + ((t2 >> 7) << 8) + (t2 & 127);
                        } else {
                            int t2 = cg - 1024;                           // v
                            hoff = 640 + ((t2 >> 7) << 8) + (t2 & 127);
                        }
                        *(__half2*)(C16 + (size_t)row * KVW + hoff) =
                            __floats2half2_rn(v0, v1);
                        continue;
                    }
                }
                size_t o = (size_t)row * Mtot + col;
                if (add1) {
                    float2 a = *(const float2*)(add1 + o);
                    v0 += a.x; v1 += a.y;
                }
                if (do_relu) { v0 = fmaxf(v0, 0.f); v1 = fmaxf(v1, 0.f); }
                *(float2*)(C + o) = make_float2(v0, v1);
                if (Cmir)
                    *(__half2*)(Cmir + o) = __floats2half2_rn(v0, v1);
            }
        }
    }
}

// ---------------------------------------------------------------------------
// fp32 -> fp16 convert (for input x mirror)
// ---------------------------------------------------------------------------
__global__ void f32_to_f16(const float* __restrict__ in, __half* __restrict__ out,
                           int n)   // n in float4 units
{
    int i = blockIdx.x * blockDim.x + threadIdx.x;
    if (i >= n) return;
    float4 v = *(const float4*)(in + i * 4);
    *(__half2*)(out + i * 4)     = __floats2half2_rn(v.x, v.y);
    *(__half2*)(out + i * 4 + 2) = __floats2half2_rn(v.z, v.w);
}

// ---------------------------------------------------------------------------
// Weight + bias packing (one kernel)
// ---------------------------------------------------------------------------
__global__ void pack_wb(const float* __restrict__ w0,
                        const float* __restrict__ w1,
                        const float* __restrict__ w2,
                        const float* __restrict__ w3,
                        const float* __restrict__ w4,
                        const float* __restrict__ b1, const float* __restrict__ b2,
                        const float* __restrict__ b3, const float* __restrict__ b4,
                        float* __restrict__ Wp, float* __restrict__ bp)
{
    int idx = blockIdx.x * blockDim.x + threadIdx.x;
    const int NW4 = HID * MPK / 4;
    if (idx < NW4) {
        int row = idx / (MPK / 4);
        int col = (idx % (MPK / 4)) * 4;
        int b   = col >> 9;
        int c   = col & 511;
        const float* srcs[5] = {w0, w1, w2, w3, w4};
        *(float4*)(Wp + (size_t)row * MPK + col) =
            *(const float4*)(srcs[b] + (size_t)row * HC + c);
    } else if (idx < NW4 + MPK) {
        int col = idx - NW4;
        int b = col >> 9, c = col & 511;
        float v = 0.f;
        if (b == 1) v = b1[c];
        else if (b == 2) v = b2[c];
        else if (b == 3) v = b3[c];
        else if (b == 4) v = b4[c];
        bp[col] = v;
    }
}

// ---------------------------------------------------------------------------
// CSR build (by dst)
// ---------------------------------------------------------------------------
__global__ void deg_count(const int* __restrict__ dst, int* __restrict__ deg)
{
    int e = blockIdx.x * blockDim.x + threadIdx.x;
    if (e < EE) atomicAdd(&deg[dst[e]], 1);
}

__global__ void scan_offsets(const int* __restrict__ deg,
                             int* __restrict__ off, int* __restrict__ cur)
{
    extern __shared__ int sdeg[];
    __shared__ int wsum[32];
    const int t    = threadIdx.x;
    const int lane = t & 31;
    const int wid  = t >> 5;
    const int CH   = (NN + 1023) / 1024;

    for (int i = t; i < NN; i += 1024) sdeg[i] = deg[i];
    __syncthreads();

    int base = t * CH;
    int s = 0;
#pragma unroll
    for (int i = 0; i < CH; i++) {
        int idx = base + i;
        if (idx < NN) s += sdeg[idx];
    }
    int v = s;
#pragma unroll
    for (int o = 1; o < 32; o <<= 1) {
        int u = __shfl_up_sync(0xffffffffu, v, o);
        if (lane >= o) v += u;
    }
    if (lane == 31) wsum[wid] = v;
    __syncthreads();
    if (wid == 0) {
        int w = wsum[lane];
#pragma unroll
        for (int o = 1; o < 32; o <<= 1) {
            int u = __shfl_up_sync(0xffffffffu, w, o);
            if (lane >= o) w += u;
        }
        wsum[lane] = w;
    }
    __syncthreads();
    int excl = v - s + (wid ? wsum[wid - 1] : 0);
#pragma unroll
    for (int i = 0; i < CH; i++) {
        int idx = base + i;
        if (idx < NN) {
            off[idx] = excl;
            cur[idx] = excl;
            excl += sdeg[idx];
        }
    }
    if (t == 1023) off[NN] = excl;
}

__global__ void build_srcs(const int* __restrict__ src, const int* __restrict__ dst,
                           int* __restrict__ cur, int* __restrict__ srcs)
{
    int e = blockIdx.x * blockDim.x + threadIdx.x;
    if (e >= EE) return;
    int pos = atomicAdd(&cur[dst[e]], 1);
    srcs[pos] = src[e];
}

// ---------------------------------------------------------------------------
// GraphConv aggregation via CSR (fp16 gather, fp32 accumulate/store)
// ---------------------------------------------------------------------------
__global__ void gconv_agg(const __half* __restrict__ in,
                          const int* __restrict__ off,
                          const int* __restrict__ srcs,
                          float* __restrict__ agg)
{
    int d = blockIdx.x;
    int c = threadIdx.x;
    int e0 = off[d], e1 = off[d + 1];
    float s = 0.f;
    int i = e0;
    for (; i + 3 < e1; i += 4) {
        int s0 = srcs[i], s1 = srcs[i + 1], s2 = srcs[i + 2], s3 = srcs[i + 3];
        s += __half2float(in[(size_t)s0 * HID + c])
           + __half2float(in[(size_t)s1 * HID + c])
           + __half2float(in[(size_t)s2 * HID + c])
           + __half2float(in[(size_t)s3 * HID + c]);
    }
    for (; i < e1; ++i)
        s += __half2float(in[(size_t)srcs[i] * HID + c]);
    agg[(size_t)d * HID + c] = s;
}

// ---------------------------------------------------------------------------
// Attention + transformer epilogue fused, 8 warps/node (2 warps per head).
// q/k/v gathered from compact fp16 kvq buffer; ts/skip from fp32 pack.
// ---------------------------------------------------------------------------
__device__ __forceinline__ float4 ld_half4(const __half* p) {
    uint2 u = *(const uint2*)p;
    float2 fa = __half22float2(*(__half2*)&u.x);
    float2 fb = __half22float2(*(__half2*)&u.y);
    return make_float4(fa.x, fa.y, fb.x, fb.y);
}

__global__ void __launch_bounds__(256)
attn_fused(const float* __restrict__ pack,
           const __half* __restrict__ kvq,
           const int* __restrict__ off,
           const int* __restrict__ srcs,
           float* __restrict__ h2)
{
    __shared__ float s_m[4], s_den[4], s_acc[4][128];

    int d    = blockIdx.x;
    int w    = threadIdx.x >> 5;
    int lane = threadIdx.x & 31;
    int h    = w & 3;
    int half = w >> 2;
    int e0 = off[d], e1 = off[d + 1];
    int emid = (e0 + e1) >> 1;
    int lo = half ? emid : e0;
    int hi = half ? e1   : emid;

    const int kvbase = 512 + h * 256;     // k at +0, v at +128 (halves)

    float4 qv = ld_half4(kvq + (size_t)d * KVW + h * HID + lane * 4);
    float4 acc = make_float4(0.f, 0.f, 0.f, 0.f);
    float mrun = NEGBIG, den = 0.f;

    int i = lo;
    for (; i + 1 < hi; i += 2) {
        int s0 = srcs[i], s1 = srcs[i + 1];
        const __half* p0 = kvq + (size_t)s0 * KVW + kvbase + lane * 4;
        const __half* p1 = kvq + (size_t)s1 * KVW + kvbase + lane * 4;
        float4 k0 = ld_half4(p0);
        float4 k1 = ld_half4(p1);
        float4 v0 = ld_half4(p0 + 128);
        float4 v1 = ld_half4(p1 + 128);
        float d0 = qv.x * k0.x + qv.y * k0.y + qv.z * k0.z + qv.w * k0.w;
        float d1 = qv.x * k1.x + qv.y * k1.y + qv.z * k1.z + qv.w * k1.w;
#pragma unroll
        for (int o = 16; o; o >>= 1) {
            d0 += __shfl_xor_sync(0xffffffffu, d0, o);
            d1 += __shfl_xor_sync(0xffffffffu, d1, o);
        }
        d0 *= 0.08838834764831843f;
        d1 *= 0.08838834764831843f;

        float mnew = fmaxf(mrun, d0);
        float corr = __expf(mrun - mnew);
        float wt   = __expf(d0 - mnew);
        den = den * corr + wt;
        acc.x = acc.x * corr + wt * v0.x;
        acc.y = acc.y * corr + wt * v0.y;
        acc.z = acc.z * corr + wt * v0.z;
        acc.w = acc.w * corr + wt * v0.w;
        mrun = mnew;

        mnew = fmaxf(mrun, d1);
        corr = __expf(mrun - mnew);
        wt   = __expf(d1 - mnew);
        den = den * corr + wt;
        acc.x = acc.x * corr + wt * v1.x;
        acc.y = acc.y * corr + wt * v1.y;
        acc.z = acc.z * corr + wt * v1.z;
        acc.w = acc.w * corr + wt * v1.w;
        mrun = mnew;
    }
    if (i < hi) {
        int s0 = srcs[i];
        const __half* p0 = kvq + (size_t)s0 * KVW + kvbase + lane * 4;
        float4 k0 = ld_half4(p0);
        float4 v0 = ld_half4(p0 + 128);
        float d0 = qv.x * k0.x + qv.y * k0.y + qv.z * k0.z + qv.w * k0.w;
#pragma unroll
        for (int o = 16; o; o >>= 1) d0 += __shfl_xor_sync(0xffffffffu, d0, o);
        d0 *= 0.08838834764831843f;
        float mnew = fmaxf(mrun, d0);
        float corr = __expf(mrun - mnew);
        float wt   = __expf(d0 - mnew);
        den = den * corr + wt;
        acc.x = acc.x * corr + wt * v0.x;
        acc.y = acc.y * corr + wt * v0.y;
        acc.z = acc.z * corr + wt * v0.z;
        acc.w = acc.w * corr + wt * v0.w;
        mrun = mnew;
    }

    if (half == 1) {
        if (lane == 0) { s_m[h] = mrun; s_den[h] = den; }
        *((float4*)&s_acc[h][0] + lane) = acc;
    }
    __syncthreads();
    if (half == 0) {
        float m1 = s_m[h], den1 = s_den[h];
        float4 a1 = *((const float4*)&s_acc[h][0] + lane);
        float mnew = fmaxf(mrun, m1);
        float c0 = __expf(mrun - mnew);
        float c1 = __expf(m1 - mnew);
        den = den * c0 + den1 * c1;
        acc.x = acc.x * c0 + a1.x * c1;
        acc.y = acc.y * c0 + a1.y * c1;
        acc.z = acc.z * c0 + a1.z * c1;
        acc.w = acc.w * c0 + a1.w * c1;

        float inv = 1.f / (den + 1e-16f);
        float4 ts = *((const float4*)(pack + 2048 + (size_t)d * MPK + h * HID) + lane);
        float4 sk = *((const float4*)(pack + 0    + (size_t)d * MPK + h * HID) + lane);
        float4 r;
        r.x = fmaxf(acc.x * inv + ts.x + sk.x, 0.f);
        r.y = fmaxf(acc.y * inv + ts.y + sk.y, 0.f);
        r.z = fmaxf(acc.z * inv + ts.z + sk.z, 0.f);
        r.w = fmaxf(acc.w * inv + ts.w + sk.w, 0.f);
        *((float4*)(h2 + (size_t)d * HC + h * HID) + lane) = r;
    }
}

// ---------------------------------------------------------------------------
// Pooling (batch sorted: accumulate runs, flush atomics on group change)
// ---------------------------------------------------------------------------
#define PB 64
__global__ void pool_accum(const float* __restrict__ h,
                           const int* __restrict__ batch,
                           float* __restrict__ pool, float* __restrict__ cnt)
{
    int c  = threadIdx.x;
    int n0 = blockIdx.x * PB;
    int n1 = min(n0 + PB, NN);
    float s = 0.f;
    int cb = batch[n0], count = 0;
    for (int n = n0; n < n1; ++n) {
        int b = batch[n];
        if (b != cb) {
            atomicAdd(&pool[cb * HID + c], s);
            if (c == 0) atomicAdd(&cnt[cb], (float)count);
            s = 0.f; count = 0; cb = b;
        }
        s += h[(size_t)n * HID + c];
        count++;
    }
    atomicAdd(&pool[cb * HID + c], s);
    if (c == 0) atomicAdd(&cnt[cb], (float)count);
}

__global__ void pool_fc(const float* __restrict__ pool,
                        const float* __restrict__ cnt,
                        const float* __restrict__ fcW,
                        const float* __restrict__ fcb,
                        float* __restrict__ out)
{
    int g = blockIdx.x;
    int c = threadIdx.x;
    float inv = 1.f / fmaxf(cnt[g], 1.f);
    float s = 0.f;
    for (int k = 0; k < HID; k++)
        s += pool[g * HID + k] * fcW[k * NCC + c];
    out[g * NCC + c] = s * inv + fcb[c];
}

// ---------------------------------------------------------------------------
// Launch
// ---------------------------------------------------------------------------
extern "C" void kernel_launch(void* const* d_in, const int* in_sizes, int n_in,
                              void* d_out, int out_size)
{
    const float* x        = (const float*)d_in[0];
    const int*   ei       = (const int*)  d_in[1];
    const int*   src      = ei;
    const int*   dst      = ei + EE;
    const int*   batch    = (const int*)  d_in[2];
    const float* c1_Wr    = (const float*)d_in[3];
    const float* c1_br    = (const float*)d_in[4];
    const float* c1_Wroot = (const float*)d_in[5];
    const float* tq_W  = (const float*)d_in[6];  const float* tq_b  = (const float*)d_in[7];
    const float* tk_W  = (const float*)d_in[8];  const float* tk_b  = (const float*)d_in[9];
    const float* tv_W  = (const float*)d_in[10]; const float* tv_b  = (const float*)d_in[11];
    const float* ts_W  = (const float*)d_in[12]; const float* ts_b  = (const float*)d_in[13];
    const float* skip_W = (const float*)d_in[14];
    const float* l1W    = (const float*)d_in[15]; const float* l1b = (const float*)d_in[16];
    const float* g1_Wr = (const float*)d_in[17]; const float* g1_br = (const float*)d_in[18];
    const float* g1_Wroot = (const float*)d_in[19];
    const float* g2_Wr = (const float*)d_in[20]; const float* g2_br = (const float*)d_in[21];
    const float* g2_Wroot = (const float*)d_in[22];
    const float* fc_W = (const float*)d_in[23]; const float* fc_b = (const float*)d_in[24];
    float* out = (float*)d_out;

    float *agg, *h, *h3, *h4, *h5, *pack, *h2, *Wpk, *bpk, *pool, *cnt;
    __half *kvq, *x16, *h316, *h416;
    int *deg, *cur, *off, *srcs;
    cudaGetSymbolAddress((void**)&agg,  g_agg);
    cudaGetSymbolAddress((void**)&h,    g_h);
    cudaGetSymbolAddress((void**)&h3,   g_h3);
    cudaGetSymbolAddress((void**)&h4,   g_h4);
    cudaGetSymbolAddress((void**)&h5,   g_h5);
    cudaGetSymbolAddress((void**)&x16,  g_x16);
    cudaGetSymbolAddress((void**)&h316, g_h316);
    cudaGetSymbolAddress((void**)&h416, g_h416);
    cudaGetSymbolAddress((void**)&pack, g_pack);
    cudaGetSymbolAddress((void**)&kvq,  g_kvq);
    cudaGetSymbolAddress((void**)&h2,   g_h2);
    cudaGetSymbolAddress((void**)&Wpk,  g_Wpk);
    cudaGetSymbolAddress((void**)&bpk,  g_bpk);
    cudaGetSymbolAddress((void**)&pool, g_pool);
    cudaGetSymbolAddress((void**)&cnt,  g_cnt);
    cudaGetSymbolAddress((void**)&deg,  g_deg);
    cudaGetSymbolAddress((void**)&cur,  g_cur);
    cudaGetSymbolAddress((void**)&off,  g_off);
    cudaGetSymbolAddress((void**)&srcs, g_srcs);

    const int SCAN_SMEM = NN * (int)sizeof(int);
    cudaFuncSetAttribute(scan_offsets, cudaFuncAttributeMaxDynamicSharedMemorySize,
                         SCAN_SMEM);

    const dim3 gb(256);
    const dim3 grid128((NN + 127) / 128, 2);
    const dim3 gridPK ((NN + 127) / 128, MPK / 64);

    // --- weight+bias packing + x fp16 mirror (independent)
    pack_wb<<<(HID * MPK / 4 + MPK + 255) / 256, 256>>>(
        skip_W, tq_W, tk_W, tv_W, ts_W, tq_b, tk_b, tv_b, ts_b, Wpk, bpk);
    f32_to_f16<<<(NN * HID / 4 + 255) / 256, 256>>>(x, x16, NN * HID / 4);

    // --- CSR build (by dst)
    cudaMemsetAsync(deg, 0, NN * sizeof(int));
    deg_count<<<(EE + 255) / 256, 256>>>(dst, deg);
    scan_offsets<<<1, 1024, SCAN_SMEM>>>(deg, off, cur);
    build_srcs<<<(EE + 255) / 256, 256>>>(src, dst, cur, srcs);

    // --- conv1: h = relu( (agg x) @ Wr + br + x @ Wroot )
    gconv_agg<<<NN, 128>>>(x16, off, srcs, agg);
    gemm_mma<<<grid128, gb>>>(agg, c1_Wr, x, c1_Wroot, c1_br,
                              nullptr, h, nullptr, nullptr, NN, 128, 128, 1);

    // --- packed projections: skip/ts -> fp32 pack, q/k/v -> fp16 kvq
    gemm_mma<<<gridPK, gb>>>(h, Wpk, nullptr, nullptr, bpk,
                             nullptr, pack, kvq, nullptr, NN, 128, MPK, 0);

    // --- attention + fused epilogue
    attn_fused<<<NN, 256>>>(pack, kvq, off, srcs, h2);

    // --- h3 = relu(h2 @ lin1_W + lin1_b)   (+ fp16 mirror for gconv gather)
    gemm_mma<<<grid128, gb>>>(h2, l1W, nullptr, nullptr, l1b,
                              nullptr, h3, nullptr, h316, NN, 512, 128, 1);

    // --- gconv l1 with residual            (+ fp16 mirror of h4)
    gconv_agg<<<NN, 128>>>(h316, off, srcs, agg);
    gemm_mma<<<grid128, gb>>>(agg, g1_Wr, h3, g1_Wroot, g1_br,
                              h3, h4, nullptr, h416, NN, 128, 128, 1);

    // --- gconv l2 with residual
    gconv_agg<<<NN, 128>>>(h416, off, srcs, agg);
    gemm_mma<<<grid128, gb>>>(agg, g2_Wr, h4, g2_Wroot, g2_br,
                              h4, h5, nullptr, nullptr, NN, 128, 128, 1);

    // --- mean pool + fc
    cudaMemsetAsync(pool, 0, (size_t)GG * HID * sizeof(float));
    cudaMemsetAsync(cnt,  0, (size_t)GG * sizeof(float));
    pool_accum<<<(NN + PB - 1) / PB, 128>>>(h5, batch, pool, cnt);
    pool_fc<<<GG, NCC>>>(pool, cnt, fc_W, fc_b, out);
}

// round 14
// speedup vs baseline: 1.0047x; 1.0047x over previous
#include <cuda_runtime.h>
#include <cuda_fp16.h>
#include <cstdint>

// Problem constants (fixed by the dataset)
#define NN   20000
#define EE   160000
#define HID  128
#define NHEADS 4
#define GG   64
#define NCC  8
#define HC   512
#define MPK  2560      // packed projection width: [skip | q | k | v | ts]
#define KVW  1536      // fp16 side-band width: [q(512) | (k128,v128) x 4 heads]
#define NEGBIG (-1.0e30f)

// ---------------------------------------------------------------------------
// Scratch (device globals: allocation-free contract)
// fp16 is the native storage format for all node-feature intermediates.
// ---------------------------------------------------------------------------
__device__ __half g_agg16[NN * HID];
__device__ __half g_x16  [NN * HID];
__device__ __half g_h16  [NN * HID];
__device__ __half g_h316 [NN * HID];
__device__ __half g_h416 [NN * HID];
__device__ __half g_h516 [NN * HID];
__device__ __half g_h216 [NN * HC];
__device__ float  g_pack [(size_t)NN * MPK];   // fp32: skip + ts slots used
__device__ __half g_kvq  [(size_t)NN * KVW];   // fp16: q,k,v compact
__device__ __half g_Wpk16[HID * MPK];
__device__ float  g_bpk  [MPK];
__device__ float  g_pool [GG * HID];
__device__ float  g_cnt  [GG];
// CSR (by dst)
__device__ int    g_deg  [NN];
__device__ int    g_cur  [NN];
__device__ int    g_off  [NN + 1];
__device__ int    g_srcs [EE];

// ---------------------------------------------------------------------------
// mma.sync fp16 GEMM + register-prefetch pipeline. A operands are fp16.
// W is fp32 (WHALF=0) or fp16 (WHALF=1).
// C[Nrows, Mtot] = op( A@W [+ A2@W2] [+bias] [+add1(fp16)] )
// Outputs: C (fp32, opt), C16 (kvq side-band, opt), Cmir (fp16, opt).
// CTA tile 128x64, BK=32. 8 warps (2m x 4n), warp tile 64x16, 2 CTAs/SM.
// ---------------------------------------------------------------------------
#define A_T  0
#define B_T  10240
#define SSTR 80

__device__ __forceinline__ unsigned pack_h16(float x, float y) {
    __half2 p = __float22half2_rn(make_float2(x, y));
    return *(unsigned*)&p;
}

__device__ __forceinline__ void mma_f16(float* c, const unsigned* a, const unsigned* b) {
    asm volatile(
        "mma.sync.aligned.m16n8k16.row.col.f32.f16.f16.f32 "
        "{%0,%1,%2,%3}, {%4,%5,%6,%7}, {%8,%9}, {%0,%1,%2,%3};"
        : "+f"(c[0]), "+f"(c[1]), "+f"(c[2]), "+f"(c[3])
        : "r"(a[0]), "r"(a[1]), "r"(a[2]), "r"(a[3]), "r"(b[0]), "r"(b[1]));
}

template<int WHALF>
__device__ __forceinline__ void load_tiles(const __half* __restrict__ Ap,
                                           const void* __restrict__ Wv,
                                           int K, int Mtot, int Nrows,
                                           int brow, int bcol, int k0, int tid,
                                           uint2 pa[4], float4 pbf[2],
                                           ushort4 pbh[2])
{
#pragma unroll
    for (int t = 0; t < 4; ++t) {
        int idx = tid + t * 256;
        int r   = idx >> 3;
        int kg  = idx & 7;
        pa[t] = make_uint2(0u, 0u);
        if (brow + r < Nrows)
            pa[t] = *(const uint2*)(Ap + (size_t)(brow + r) * K + k0 + kg * 4);
    }
#pragma unroll
    for (int t = 0; t < 2; ++t) {
        int idx = tid + t * 256;
        int n   = idx & 63;
        int kg  = idx >> 6;
        if (WHALF) {
            const __half* wp = (const __half*)Wv
                             + (size_t)(k0 + kg * 4) * Mtot + bcol + n;
            pbh[t].x = *(const unsigned short*)wp;
            pbh[t].y = *(const unsigned short*)(wp + Mtot);
            pbh[t].z = *(const unsigned short*)(wp + 2 * (size_t)Mtot);
            pbh[t].w = *(const unsigned short*)(wp + 3 * (size_t)Mtot);
        } else {
            const float* wp = (const float*)Wv
                            + (size_t)(k0 + kg * 4) * Mtot + bcol + n;
            pbf[t] = make_float4(wp[0], wp[Mtot], wp[2 * (size_t)Mtot],
                                 wp[3 * (size_t)Mtot]);
        }
    }
}

template<int WHALF>
__global__ void __launch_bounds__(256, 2)
gemm_mma(const __half* __restrict__ A,  const void* __restrict__ W,
         const __half* __restrict__ A2, const void* __restrict__ W2,
         const float* __restrict__ bias,
         const __half* __restrict__ add1,
         float* __restrict__ C, __half* __restrict__ C16,
         __half* __restrict__ Cmir,
         int Nrows, int K, int Mtot, int do_relu)
{
    __shared__ __align__(16) char smem[15360];

    const int tid    = threadIdx.x;
    const int wid    = tid >> 5;
    const int lane   = tid & 31;
    const int warp_m = wid >> 2;
    const int warp_n = wid & 3;
    const int g      = lane >> 2;
    const int t4     = (lane & 3) * 4;
    const int brow   = blockIdx.x * 128;
    const int bcol   = blockIdx.y * 64;

    float acc[4][2][4];
#pragma unroll
    for (int i = 0; i < 4; i++)
#pragma unroll
        for (int j = 0; j < 2; j++)
#pragma unroll
            for (int r = 0; r < 4; r++) acc[i][j][r] = 0.f;

    const int kch = K >> 5;
    const int nch = A2 ? kch * 2 : kch;

    uint2 pa[4]; float4 pbf[2]; ushort4 pbh[2];
    load_tiles<WHALF>(A, W, K, Mtot, Nrows, brow, bcol, 0, tid, pa, pbf, pbh);

    for (int c = 0; c < nch; ++c) {
        __syncthreads();   // previous compute done; smem free

        // ---- store prefetched regs -> smem (A is already fp16)
#pragma unroll
        for (int t = 0; t < 4; ++t) {
            int idx = tid + t * 256;
            int r   = idx >> 3;
            int kg  = idx & 7;
            *(uint2*)(smem + A_T + r * SSTR + kg * 8) = pa[t];
        }
#pragma unroll
        for (int t = 0; t < 2; ++t) {
            int idx = tid + t * 256;
            int n   = idx & 63;
            int kg  = idx >> 6;
            uint2 bb;
            if (WHALF)
                bb = make_uint2((unsigned)pbh[t].x | ((unsigned)pbh[t].y << 16),
                                (unsigned)pbh[t].z | ((unsigned)pbh[t].w << 16));
            else
                bb = make_uint2(pack_h16(pbf[t].x, pbf[t].y),
                                pack_h16(pbf[t].z, pbf[t].w));
            *(uint2*)(smem + B_T + n * SSTR + kg * 8) = bb;
        }

        // ---- issue next chunk's global loads (overlap with MMA below)
        if (c + 1 < nch) {
            int cn   = c + 1;
            int pass = cn / kch;
            int k0   = (cn % kch) * 32;
            load_tiles<WHALF>(pass ? A2 : A, pass ? W2 : W, K, Mtot, Nrows,
                              brow, bcol, k0, tid, pa, pbf, pbh);
        }
        __syncthreads();   // smem tiles ready

        // ---- compute: 2 k-steps of 16
#pragma unroll
        for (int ks = 0; ks < 2; ++ks) {
            const int ko = ks * 32;
            unsigned aF[4][4], bF[2][2];
#pragma unroll
            for (int nt = 0; nt < 2; ++nt) {
                int nb = (warp_n * 16 + nt * 8 + g) * SSTR + t4 + ko;
                bF[nt][0] = *(const unsigned*)(smem + B_T + nb);
                bF[nt][1] = *(const unsigned*)(smem + B_T + nb + 16);
            }
#pragma unroll
            for (int mt = 0; mt < 4; ++mt) {
                int mb = (warp_m * 64 + mt * 16 + g) * SSTR + t4 + ko;
                aF[mt][0] = *(const unsigned*)(smem + A_T + mb);
                aF[mt][1] = *(const unsigned*)(smem + A_T + mb + 8 * SSTR);
                aF[mt][2] = *(const unsigned*)(smem + A_T + mb + 16);
                aF[mt][3] = *(const unsigned*)(smem + A_T + mb + 8 * SSTR + 16);
            }
#pragma unroll
            for (int mt = 0; mt < 4; ++mt)
#pragma unroll
                for (int nt = 0; nt < 2; ++nt)
                    mma_f16(acc[mt][nt], aF[mt], bF[nt]);
        }
    }

    // ---- epilogue
#pragma unroll
    for (int mt = 0; mt < 4; ++mt) {
#pragma unroll
        for (int nt = 0; nt < 2; ++nt) {
            int col = bcol + warp_n * 16 + nt * 8 + (lane & 3) * 2;
#pragma unroll
            for (int half = 0; half < 2; ++half) {
                int row = brow + warp_m * 64 + mt * 16 + g + half * 8;
                if (row >= Nrows) continue;
                float v0 = acc[mt][nt][half * 2 + 0];
                float v1 = acc[mt][nt][half * 2 + 1];
                if (bias) {
                    float2 b = *(const float2*)(bias + col);
                    v0 += b.x; v1 += b.y;
                }
                // fp16 side-band for q/k/v columns (pack GEMM only)
                if (C16) {
                    int cg = col - 512;
                    if (cg >= 0 && cg < 1536) {
                        int hoff;
                        if (cg < 512) {
                            hoff = cg;                                    // q
                        } else if (cg < 1024) {
                            int t2 = cg - 512;                            // k
                            hoff = 512 + ((t2 >> 7) << 8) + (t2 & 127);
                        } else {
                            int t2 = cg - 1024;                           // v
                            hoff = 640 + ((t2 >> 7) << 8) + (t2 & 127);
                        }
                        *(__half2*)(C16 + (size_t)row * KVW + hoff) =
                            __floats2half2_rn(v0, v1);
                        continue;
                    }
                }
                size_t o = (size_t)row * Mtot + col;
                if (add1) {
                    float2 a = __half22float2(*(const __half2*)(add1 + o));
                    v0 += a.x; v1 += a.y;
                }
                if (do_relu) { v0 = fmaxf(v0, 0.f); v1 = fmaxf(v1, 0.f); }
                if (C)    *(float2*)(C + o) = make_float2(v0, v1);
                if (Cmir) *(__half2*)(Cmir + o) = __floats2half2_rn(v0, v1);
            }
        }
    }
}

// ---------------------------------------------------------------------------
// fp32 -> fp16 convert (for input x mirror)
// ---------------------------------------------------------------------------
__global__ void f32_to_f16(const float* __restrict__ in, __half* __restrict__ out,
                           int n)   // n in float4 units
{
    int i = blockIdx.x * blockDim.x + threadIdx.x;
    if (i >= n) return;
    float4 v = *(const float4*)(in + i * 4);
    *(__half2*)(out + i * 4)     = __floats2half2_rn(v.x, v.y);
    *(__half2*)(out + i * 4 + 2) = __floats2half2_rn(v.z, v.w);
}

// ---------------------------------------------------------------------------
// Weight (fp16) + bias (fp32) packing, one kernel
// ---------------------------------------------------------------------------
__global__ void pack_wb(const float* __restrict__ w0,
                        const float* __restrict__ w1,
                        const float* __restrict__ w2,
                        const float* __restrict__ w3,
                        const float* __restrict__ w4,
                        const float* __restrict__ b1, const float* __restrict__ b2,
                        const float* __restrict__ b3, const float* __restrict__ b4,
                        __half* __restrict__ Wp, float* __restrict__ bp)
{
    int idx = blockIdx.x * blockDim.x + threadIdx.x;
    const int NW4 = HID * MPK / 4;
    if (idx < NW4) {
        int row = idx / (MPK / 4);
        int col = (idx % (MPK / 4)) * 4;
        int b   = col >> 9;
        int c   = col & 511;
        const float* srcs[5] = {w0, w1, w2, w3, w4};
        float4 v = *(const float4*)(srcs[b] + (size_t)row * HC + c);
        __half2 h0 = __floats2half2_rn(v.x, v.y);
        __half2 h1 = __floats2half2_rn(v.z, v.w);
        *(uint2*)(Wp + (size_t)row * MPK + col) =
            make_uint2(*(unsigned*)&h0, *(unsigned*)&h1);
    } else if (idx < NW4 + MPK) {
        int col = idx - NW4;
        int b = col >> 9, c = col & 511;
        float v = 0.f;
        if (b == 1) v = b1[c];
        else if (b == 2) v = b2[c];
        else if (b == 3) v = b3[c];
        else if (b == 4) v = b4[c];
        bp[col] = v;
    }
}

// ---------------------------------------------------------------------------
// CSR build (by dst)
// ---------------------------------------------------------------------------
__global__ void deg_count(const int* __restrict__ dst, int* __restrict__ deg)
{
    int e = blockIdx.x * blockDim.x + threadIdx.x;
    if (e < EE) atomicAdd(&deg[dst[e]], 1);
}

__global__ void scan_offsets(const int* __restrict__ deg,
                             int* __restrict__ off, int* __restrict__ cur)
{
    extern __shared__ int sdeg[];
    __shared__ int wsum[32];
    const int t    = threadIdx.x;
    const int lane = t & 31;
    const int wid  = t >> 5;
    const int CH   = (NN + 1023) / 1024;

    for (int i = t; i < NN; i += 1024) sdeg[i] = deg[i];
    __syncthreads();

    int base = t * CH;
    int s = 0;
#pragma unroll
    for (int i = 0; i < CH; i++) {
        int idx = base + i;
        if (idx < NN) s += sdeg[idx];
    }
    int v = s;
#pragma unroll
    for (int o = 1; o < 32; o <<= 1) {
        int u = __shfl_up_sync(0xffffffffu, v, o);
        if (lane >= o) v += u;
    }
    if (lane == 31) wsum[wid] = v;
    __syncthreads();
    if (wid == 0) {
        int w = wsum[lane];
#pragma unroll
        for (int o = 1; o < 32; o <<= 1) {
            int u = __shfl_up_sync(0xffffffffu, w, o);
            if (lane >= o) w += u;
        }
        wsum[lane] = w;
    }
    __syncthreads();
    int excl = v - s + (wid ? wsum[wid - 1] : 0);
#pragma unroll
    for (int i = 0; i < CH; i++) {
        int idx = base + i;
        if (idx < NN) {
            off[idx] = excl;
            cur[idx] = excl;
            excl += sdeg[idx];
        }
    }
    if (t == 1023) off[NN] = excl;
}

__global__ void build_srcs(const int* __restrict__ src, const int* __restrict__ dst,
                           int* __restrict__ cur, int* __restrict__ srcs)
{
    int e = blockIdx.x * blockDim.x + threadIdx.x;
    if (e >= EE) return;
    int pos = atomicAdd(&cur[dst[e]], 1);
    srcs[pos] = src[e];
}

// ---------------------------------------------------------------------------
// GraphConv aggregation via CSR (fp16 gather, fp32 accumulate, fp16 store)
// ---------------------------------------------------------------------------
__global__ void gconv_agg(const __half* __restrict__ in,
                          const int* __restrict__ off,
                          const int* __restrict__ srcs,
                          __half* __restrict__ agg)
{
    int d = blockIdx.x;
    int c = threadIdx.x;
    int e0 = off[d], e1 = off[d + 1];
    float s = 0.f;
    int i = e0;
    for (; i + 3 < e1; i += 4) {
        int s0 = srcs[i], s1 = srcs[i + 1], s2 = srcs[i + 2], s3 = srcs[i + 3];
        s += __half2float(in[(size_t)s0 * HID + c])
           + __half2float(in[(size_t)s1 * HID + c])
           + __half2float(in[(size_t)s2 * HID + c])
           + __half2float(in[(size_t)s3 * HID + c]);
    }
    for (; i < e1; ++i)
        s += __half2float(in[(size_t)srcs[i] * HID + c]);
    agg[(size_t)d * HID + c] = __float2half_rn(s);
}

// ---------------------------------------------------------------------------
// Attention + transformer epilogue fused, 8 warps/node (2 warps per head).
// q/k/v gathered from compact fp16 kvq; ts/skip from fp32 pack; h2 out fp16.
// ---------------------------------------------------------------------------
__device__ __forceinline__ float4 ld_half4(const __half* p) {
    uint2 u = *(const uint2*)p;
    float2 fa = __half22float2(*(__half2*)&u.x);
    float2 fb = __half22float2(*(__half2*)&u.y);
    return make_float4(fa.x, fa.y, fb.x, fb.y);
}

__global__ void __launch_bounds__(256)
attn_fused(const float* __restrict__ pack,
           const __half* __restrict__ kvq,
           const int* __restrict__ off,
           const int* __restrict__ srcs,
           __half* __restrict__ h2)
{
    __shared__ float s_m[4], s_den[4], s_acc[4][128];

    int d    = blockIdx.x;
    int w    = threadIdx.x >> 5;
    int lane = threadIdx.x & 31;
    int h    = w & 3;
    int half = w >> 2;
    int e0 = off[d], e1 = off[d + 1];
    int emid = (e0 + e1) >> 1;
    int lo = half ? emid : e0;
    int hi = half ? e1   : emid;

    const int kvbase = 512 + h * 256;     // k at +0, v at +128 (halves)

    float4 qv = ld_half4(kvq + (size_t)d * KVW + h * HID + lane * 4);
    float4 acc = make_float4(0.f, 0.f, 0.f, 0.f);
    float mrun = NEGBIG, den = 0.f;

    int i = lo;
    for (; i + 1 < hi; i += 2) {
        int s0 = srcs[i], s1 = srcs[i + 1];
        const __half* p0 = kvq + (size_t)s0 * KVW + kvbase + lane * 4;
        const __half* p1 = kvq + (size_t)s1 * KVW + kvbase + lane * 4;
        float4 k0 = ld_half4(p0);
        float4 k1 = ld_half4(p1);
        float4 v0 = ld_half4(p0 + 128);
        float4 v1 = ld_half4(p1 + 128);
        float d0 = qv.x * k0.x + qv.y * k0.y + qv.z * k0.z + qv.w * k0.w;
        float d1 = qv.x * k1.x + qv.y * k1.y + qv.z * k1.z + qv.w * k1.w;
#pragma unroll
        for (int o = 16; o; o >>= 1) {
            d0 += __shfl_xor_sync(0xffffffffu, d0, o);
            d1 += __shfl_xor_sync(0xffffffffu, d1, o);
        }
        d0 *= 0.08838834764831843f;
        d1 *= 0.08838834764831843f;

        float mnew = fmaxf(mrun, d0);
        float corr = __expf(mrun - mnew);
        float wt   = __expf(d0 - mnew);
        den = den * corr + wt;
        acc.x = acc.x * corr + wt * v0.x;
        acc.y = acc.y * corr + wt * v0.y;
        acc.z = acc.z * corr + wt * v0.z;
        acc.w = acc.w * corr + wt * v0.w;
        mrun = mnew;

        mnew = fmaxf(mrun, d1);
        corr = __expf(mrun - mnew);
        wt   = __expf(d1 - mnew);
        den = den * corr + wt;
        acc.x = acc.x * corr + wt * v1.x;
        acc.y = acc.y * corr + wt * v1.y;
        acc.z = acc.z * corr + wt * v1.z;
        acc.w = acc.w * corr + wt * v1.w;
        mrun = mnew;
    }
    if (i < hi) {
        int s0 = srcs[i];
        const __half* p0 = kvq + (size_t)s0 * KVW + kvbase + lane * 4;
        float4 k0 = ld_half4(p0);
        float4 v0 = ld_half4(p0 + 128);
        float d0 = qv.x * k0.x + qv.y * k0.y + qv.z * k0.z + qv.w * k0.w;
#pragma unroll
        for (int o = 16; o; o >>= 1) d0 += __shfl_xor_sync(0xffffffffu, d0, o);
        d0 *= 0.08838834764831843f;
        float mnew = fmaxf(mrun, d0);
        float corr = __expf(mrun - mnew);
        float wt   = __expf(d0 - mnew);
        den = den * corr + wt;
        acc.x = acc.x * corr + wt * v0.x;
        acc.y = acc.y * corr + wt * v0.y;
        acc.z = acc.z * corr + wt * v0.z;
        acc.w = acc.w * corr + wt * v0.w;
        mrun = mnew;
    }

    if (half == 1) {
        if (lane == 0) { s_m[h] = mrun; s_den[h] = den; }
        *((float4*)&s_acc[h][0] + lane) = acc;
    }
    __syncthreads();
    if (half == 0) {
        float m1 = s_m[h], den1 = s_den[h];
        float4 a1 = *((const float4*)&s_acc[h][0] + lane);
        float mnew = fmaxf(mrun, m1);
        float c0 = __expf(mrun - mnew);
        float c1 = __expf(m1 - mnew);
        den = den * c0 + den1 * c1;
        acc.x = acc.x * c0 + a1.x * c1;
        acc.y = acc.y * c0 + a1.y * c1;
        acc.z = acc.z * c0 + a1.z * c1;
        acc.w = acc.w * c0 + a1.w * c1;

        float inv = 1.f / (den + 1e-16f);
        float4 ts = *((const float4*)(pack + 2048 + (size_t)d * MPK + h * HID) + lane);
        float4 sk = *((const float4*)(pack + 0    + (size_t)d * MPK + h * HID) + lane);
        float r0 = fmaxf(acc.x * inv + ts.x + sk.x, 0.f);
        float r1 = fmaxf(acc.y * inv + ts.y + sk.y, 0.f);
        float r2 = fmaxf(acc.z * inv + ts.z + sk.z, 0.f);
        float r3 = fmaxf(acc.w * inv + ts.w + sk.w, 0.f);
        __half2 q0 = __floats2half2_rn(r0, r1);
        __half2 q1 = __floats2half2_rn(r2, r3);
        *(uint2*)(h2 + (size_t)d * HC + h * HID + lane * 4) =
            make_uint2(*(unsigned*)&q0, *(unsigned*)&q1);
    }
}

// ---------------------------------------------------------------------------
// Pooling (fp16 input; batch sorted: accumulate runs, flush on group change)
// ---------------------------------------------------------------------------
#define PB 64
__global__ void pool_accum(const __half* __restrict__ h,
                           const int* __restrict__ batch,
                           float* __restrict__ pool, float* __restrict__ cnt)
{
    int c  = threadIdx.x;
    int n0 = blockIdx.x * PB;
    int n1 = min(n0 + PB, NN);
    float s = 0.f;
    int cb = batch[n0], count = 0;
    for (int n = n0; n < n1; ++n) {
        int b = batch[n];
        if (b != cb) {
            atomicAdd(&pool[cb * HID + c], s);
            if (c == 0) atomicAdd(&cnt[cb], (float)count);
            s = 0.f; count = 0; cb = b;
        }
        s += __half2float(h[(size_t)n * HID + c]);
        count++;
    }
    atomicAdd(&pool[cb * HID + c], s);
    if (c == 0) atomicAdd(&cnt[cb], (float)count);
}

__global__ void pool_fc(const float* __restrict__ pool,
                        const float* __restrict__ cnt,
                        const float* __restrict__ fcW,
                        const float* __restrict__ fcb,
                        float* __restrict__ out)
{
    int g = blockIdx.x;
    int c = threadIdx.x;
    float inv = 1.f / fmaxf(cnt[g], 1.f);
    float s = 0.f;
    for (int k = 0; k < HID; k++)
        s += pool[g * HID + k] * fcW[k * NCC + c];
    out[g * NCC + c] = s * inv + fcb[c];
}

// ---------------------------------------------------------------------------
// Launch
// ---------------------------------------------------------------------------
extern "C" void kernel_launch(void* const* d_in, const int* in_sizes, int n_in,
                              void* d_out, int out_size)
{
    const float* x        = (const float*)d_in[0];
    const int*   ei       = (const int*)  d_in[1];
    const int*   src      = ei;
    const int*   dst      = ei + EE;
    const int*   batch    = (const int*)  d_in[2];
    const float* c1_Wr    = (const float*)d_in[3];
    const float* c1_br    = (const float*)d_in[4];
    const float* c1_Wroot = (const float*)d_in[5];
    const float* tq_W  = (const float*)d_in[6];  const float* tq_b  = (const float*)d_in[7];
    const float* tk_W  = (const float*)d_in[8];  const float* tk_b  = (const float*)d_in[9];
    const float* tv_W  = (const float*)d_in[10]; const float* tv_b  = (const float*)d_in[11];
    const float* ts_W  = (const float*)d_in[12]; const float* ts_b  = (const float*)d_in[13];
    const float* skip_W = (const float*)d_in[14];
    const float* l1W    = (const float*)d_in[15]; const float* l1b = (const float*)d_in[16];
    const float* g1_Wr = (const float*)d_in[17]; const float* g1_br = (const float*)d_in[18];
    const float* g1_Wroot = (const float*)d_in[19];
    const float* g2_Wr = (const float*)d_in[20]; const float* g2_br = (const float*)d_in[21];
    const float* g2_Wroot = (const float*)d_in[22];
    const float* fc_W = (const float*)d_in[23]; const float* fc_b = (const float*)d_in[24];
    float* out = (float*)d_out;

    float *pack, *Wb, *bpk, *pool, *cnt;
    __half *agg16, *x16, *h16, *h316, *h416, *h516, *h216, *kvq, *Wpk16;
    int *deg, *cur, *off, *srcs;
    cudaGetSymbolAddress((void**)&agg16, g_agg16);
    cudaGetSymbolAddress((void**)&x16,   g_x16);
    cudaGetSymbolAddress((void**)&h16,   g_h16);
    cudaGetSymbolAddress((void**)&h316,  g_h316);
    cudaGetSymbolAddress((void**)&h416,  g_h416);
    cudaGetSymbolAddress((void**)&h516,  g_h516);
    cudaGetSymbolAddress((void**)&h216,  g_h216);
    cudaGetSymbolAddress((void**)&pack,  g_pack);
    cudaGetSymbolAddress((void**)&kvq,   g_kvq);
    cudaGetSymbolAddress((void**)&Wpk16, g_Wpk16);
    cudaGetSymbolAddress((void**)&bpk,   g_bpk);
    cudaGetSymbolAddress((void**)&pool,  g_pool);
    cudaGetSymbolAddress((void**)&cnt,   g_cnt);
    cudaGetSymbolAddress((void**)&deg,   g_deg);
    cudaGetSymbolAddress((void**)&cur,   g_cur);
    cudaGetSymbolAddress((void**)&off,   g_off);
    cudaGetSymbolAddress((void**)&srcs,  g_srcs);
    (void)Wb;

    const int SCAN_SMEM = NN * (int)sizeof(int);
    cudaFuncSetAttribute(scan_offsets, cudaFuncAttributeMaxDynamicSharedMemorySize,
                         SCAN_SMEM);

    const dim3 gb(256);
    const dim3 grid128((NN + 127) / 128, 2);
    const dim3 gridPK ((NN + 127) / 128, MPK / 64);

    // --- weight+bias packing + x fp16 convert (independent)
    pack_wb<<<(HID * MPK / 4 + MPK + 255) / 256, 256>>>(
        skip_W, tq_W, tk_W, tv_W, ts_W, tq_b, tk_b, tv_b, ts_b, Wpk16, bpk);
    f32_to_f16<<<(NN * HID / 4 + 255) / 256, 256>>>(x, x16, NN * HID / 4);

    // --- CSR build (by dst)
    cudaMemsetAsync(deg, 0, NN * sizeof(int));
    deg_count<<<(EE + 255) / 256, 256>>>(dst, deg);
    scan_offsets<<<1, 1024, SCAN_SMEM>>>(deg, off, cur);
    build_srcs<<<(EE + 255) / 256, 256>>>(src, dst, cur, srcs);

    // --- conv1: h16 = relu( (agg x) @ Wr + br + x @ Wroot )
    gconv_agg<<<NN, 128>>>(x16, off, srcs, agg16);
    gemm_mma<0><<<grid128, gb>>>(agg16, c1_Wr, x16, c1_Wroot, c1_br,
                                 nullptr, nullptr, nullptr, h16,
                                 NN, 128, 128, 1);

    // --- packed projections: skip/ts -> fp32 pack, q/k/v -> fp16 kvq
    gemm_mma<1><<<gridPK, gb>>>(h16, Wpk16, nullptr, nullptr, bpk,
                                nullptr, pack, kvq, nullptr,
                                NN, 128, MPK, 0);

    // --- attention + fused epilogue -> h2 (fp16)
    attn_fused<<<NN, 256>>>(pack, kvq, off, srcs, h216);

    // --- h3 = relu(h2 @ lin1_W + lin1_b)  (fp16 out)
    gemm_mma<0><<<grid128, gb>>>(h216, l1W, nullptr, nullptr, l1b,
                                 nullptr, nullptr, nullptr, h316,
                                 NN, 512, 128, 1);

    // --- gconv l1 with residual (fp16 chain)
    gconv_agg<<<NN, 128>>>(h316, off, srcs, agg16);
    gemm_mma<0><<<grid128, gb>>>(agg16, g1_Wr, h316, g1_Wroot, g1_br,
                                 h316, nullptr, nullptr, h416,
                                 NN, 128, 128, 1);

    // --- gconv l2 with residual
    gconv_agg<<<NN, 128>>>(h416, off, srcs, agg16);
    gemm_mma<0><<<grid128, gb>>>(agg16, g2_Wr, h416, g2_Wroot, g2_br,
                                 h416, nullptr, nullptr, h516,
                                 NN, 128, 128, 1);

    // --- mean pool + fc
    cudaMemsetAsync(pool, 0, (size_t)GG * HID * sizeof(float));
    cudaMemsetAsync(cnt,  0, (size_t)GG * sizeof(float));
    pool_accum<<<(NN + PB - 1) / PB, 128>>>(h516, batch, pool, cnt);
    pool_fc<<<GG, NCC>>>(pool, cnt, fc_W, fc_b, out);
}

// round 15
// speedup vs baseline: 1.1369x; 1.1316x over previous
#include <cuda_runtime.h>
#include <cuda_fp16.h>
#include <cstdint>

// Problem constants (fixed by the dataset)
#define NN   20000
#define EE   160000
#define HID  128
#define NHEADS 4
#define GG   64
#define NCC  8
#define HC   512
#define MPK  2560      // packed projection width: [skip | q | k | v | ts]
#define KVW  1536      // fp16 side-band width: [q(512) | (k128,v128) x 4 heads]
#define NEGBIG (-1.0e30f)
#define BM   160       // GEMM row tile: 20000 % 160 == 0 -> 125 tiles, no bounds checks

// ---------------------------------------------------------------------------
// Scratch (device globals: allocation-free contract)
// ---------------------------------------------------------------------------
__device__ __half g_agg16[NN * HID];
__device__ __half g_x16  [NN * HID];
__device__ __half g_h16  [NN * HID];
__device__ __half g_h316 [NN * HID];
__device__ __half g_h416 [NN * HID];
__device__ __half g_h516 [NN * HID];
__device__ __half g_h216 [NN * HC];
__device__ float  g_pack [(size_t)NN * MPK];   // fp32: skip + ts slots used
__device__ __half g_kvq  [(size_t)NN * KVW];   // fp16: q,k,v compact
__device__ __half g_Wpk16[HID * MPK];
__device__ float  g_bpk  [MPK];
__device__ float  g_pool [GG * HID];
__device__ float  g_cnt  [GG];
// CSR (by dst)
__device__ int    g_deg  [NN];
__device__ int    g_cur  [NN];
__device__ int    g_off  [NN + 1];
__device__ int    g_srcs [EE];

// ---------------------------------------------------------------------------
// mma.sync fp16 GEMM + register-prefetch pipeline. A operands fp16.
// W fp32 (WHALF=0) or fp16 (WHALF=1).
// C[Nrows=20000, Mtot] = op( A@W [+ A2@W2] [+bias] [+add1(fp16)] )
// Outputs: C (fp32, opt), C16 (kvq side-band, opt), Cmir (fp16, opt).
// CTA tile 160x64, BK=32. 8 warps (2m x 4n), warp tile 80x16, 2 CTAs/SM.
// grid.x = 125 exactly -> Mtot=128 GEMMs run in a single wave (250 CTAs).
// ---------------------------------------------------------------------------
#define A_T  0
#define B_T  12800       // 160 rows * 80B
#define SSTR 80

__device__ __forceinline__ unsigned pack_h16(float x, float y) {
    __half2 p = __float22half2_rn(make_float2(x, y));
    return *(unsigned*)&p;
}

__device__ __forceinline__ void mma_f16(float* c, const unsigned* a, const unsigned* b) {
    asm volatile(
        "mma.sync.aligned.m16n8k16.row.col.f32.f16.f16.f32 "
        "{%0,%1,%2,%3}, {%4,%5,%6,%7}, {%8,%9}, {%0,%1,%2,%3};"
        : "+f"(c[0]), "+f"(c[1]), "+f"(c[2]), "+f"(c[3])
        : "r"(a[0]), "r"(a[1]), "r"(a[2]), "r"(a[3]), "r"(b[0]), "r"(b[1]));
}

template<int WHALF>
__device__ __forceinline__ void load_tiles(const __half* __restrict__ Ap,
                                           const void* __restrict__ Wv,
                                           int K, int Mtot,
                                           int brow, int bcol, int k0, int tid,
                                           uint2 pa[5], float4 pbf[2],
                                           ushort4 pbh[2])
{
#pragma unroll
    for (int t = 0; t < 5; ++t) {
        int idx = tid + t * 256;          // 0..1279
        int r   = idx >> 3;               // 0..159
        int kg  = idx & 7;
        pa[t] = *(const uint2*)(Ap + (size_t)(brow + r) * K + k0 + kg * 4);
    }
#pragma unroll
    for (int t = 0; t < 2; ++t) {
        int idx = tid + t * 256;
        int n   = idx & 63;
        int kg  = idx >> 6;
        if (WHALF) {
            const __half* wp = (const __half*)Wv
                             + (size_t)(k0 + kg * 4) * Mtot + bcol + n;
            pbh[t].x = *(const unsigned short*)wp;
            pbh[t].y = *(const unsigned short*)(wp + Mtot);
            pbh[t].z = *(const unsigned short*)(wp + 2 * (size_t)Mtot);
            pbh[t].w = *(const unsigned short*)(wp + 3 * (size_t)Mtot);
        } else {
            const float* wp = (const float*)Wv
                            + (size_t)(k0 + kg * 4) * Mtot + bcol + n;
            pbf[t] = make_float4(wp[0], wp[Mtot], wp[2 * (size_t)Mtot],
                                 wp[3 * (size_t)Mtot]);
        }
    }
}

template<int WHALF>
__global__ void __launch_bounds__(256, 2)
gemm_mma(const __half* __restrict__ A,  const void* __restrict__ W,
         const __half* __restrict__ A2, const void* __restrict__ W2,
         const float* __restrict__ bias,
         const __half* __restrict__ add1,
         float* __restrict__ C, __half* __restrict__ C16,
         __half* __restrict__ Cmir,
         int K, int Mtot, int do_relu)
{
    __shared__ __align__(16) char smem[17920];   // A 12800 + B 5120

    const int tid    = threadIdx.x;
    const int wid    = tid >> 5;
    const int lane   = tid & 31;
    const int warp_m = wid >> 2;          // 0..1 (80 rows each)
    const int warp_n = wid & 3;           // 0..3 (16 cols each)
    const int g      = lane >> 2;
    const int t4     = (lane & 3) * 4;
    const int brow   = blockIdx.x * BM;
    const int bcol   = blockIdx.y * 64;

    float acc[5][2][4];
#pragma unroll
    for (int i = 0; i < 5; i++)
#pragma unroll
        for (int j = 0; j < 2; j++)
#pragma unroll
            for (int r = 0; r < 4; r++) acc[i][j][r] = 0.f;

    const int kch = K >> 5;
    const int nch = A2 ? kch * 2 : kch;

    uint2 pa[5]; float4 pbf[2]; ushort4 pbh[2];
    load_tiles<WHALF>(A, W, K, Mtot, brow, bcol, 0, tid, pa, pbf, pbh);

    for (int c = 0; c < nch; ++c) {
        __syncthreads();   // previous compute done; smem free

        // ---- store prefetched regs -> smem
#pragma unroll
        for (int t = 0; t < 5; ++t) {
            int idx = tid + t * 256;
            int r   = idx >> 3;
            int kg  = idx & 7;
            *(uint2*)(smem + A_T + r * SSTR + kg * 8) = pa[t];
        }
#pragma unroll
        for (int t = 0; t < 2; ++t) {
            int idx = tid + t * 256;
            int n   = idx & 63;
            int kg  = idx >> 6;
            uint2 bb;
            if (WHALF)
                bb = make_uint2((unsigned)pbh[t].x | ((unsigned)pbh[t].y << 16),
                                (unsigned)pbh[t].z | ((unsigned)pbh[t].w << 16));
            else
                bb = make_uint2(pack_h16(pbf[t].x, pbf[t].y),
                                pack_h16(pbf[t].z, pbf[t].w));
            *(uint2*)(smem + B_T + n * SSTR + kg * 8) = bb;
        }

        // ---- issue next chunk's global loads (overlap with MMA below)
        if (c + 1 < nch) {
            int cn   = c + 1;
            int pass = cn / kch;
            int k0   = (cn % kch) * 32;
            load_tiles<WHALF>(pass ? A2 : A, pass ? W2 : W, K, Mtot,
                              brow, bcol, k0, tid, pa, pbf, pbh);
        }
        __syncthreads();   // smem tiles ready

        // ---- compute: 2 k-steps of 16
#pragma unroll
        for (int ks = 0; ks < 2; ++ks) {
            const int ko = ks * 32;
            unsigned aF[5][4], bF[2][2];
#pragma unroll
            for (int nt = 0; nt < 2; ++nt) {
                int nb = (warp_n * 16 + nt * 8 + g) * SSTR + t4 + ko;
                bF[nt][0] = *(const unsigned*)(smem + B_T + nb);
                bF[nt][1] = *(const unsigned*)(smem + B_T + nb + 16);
            }
#pragma unroll
            for (int mt = 0; mt < 5; ++mt) {
                int mb = (warp_m * 80 + mt * 16 + g) * SSTR + t4 + ko;
                aF[mt][0] = *(const unsigned*)(smem + A_T + mb);
                aF[mt][1] = *(const unsigned*)(smem + A_T + mb + 8 * SSTR);
                aF[mt][2] = *(const unsigned*)(smem + A_T + mb + 16);
                aF[mt][3] = *(const unsigned*)(smem + A_T + mb + 8 * SSTR + 16);
            }
#pragma unroll
            for (int mt = 0; mt < 5; ++mt)
#pragma unroll
                for (int nt = 0; nt < 2; ++nt)
                    mma_f16(acc[mt][nt], aF[mt], bF[nt]);
        }
    }

    // ---- epilogue (no row bounds checks: 20000 % 160 == 0)
#pragma unroll
    for (int mt = 0; mt < 5; ++mt) {
#pragma unroll
        for (int nt = 0; nt < 2; ++nt) {
            int col = bcol + warp_n * 16 + nt * 8 + (lane & 3) * 2;
#pragma unroll
            for (int half = 0; half < 2; ++half) {
                int row = brow + warp_m * 80 + mt * 16 + g + half * 8;
                float v0 = acc[mt][nt][half * 2 + 0];
                float v1 = acc[mt][nt][half * 2 + 1];
                if (bias) {
                    float2 b = *(const float2*)(bias + col);
                    v0 += b.x; v1 += b.y;
                }
                // fp16 side-band for q/k/v columns (pack GEMM only)
                if (C16) {
                    int cg = col - 512;
                    if (cg >= 0 && cg < 1536) {
                        int hoff;
                        if (cg < 512) {
                            hoff = cg;                                    // q
                        } else if (cg < 1024) {
                            int t2 = cg - 512;                            // k
                            hoff = 512 + ((t2 >> 7) << 8) + (t2 & 127);
                        } else {
                            int t2 = cg - 1024;                           // v
                            hoff = 640 + ((t2 >> 7) << 8) + (t2 & 127);
                        }
                        *(__half2*)(C16 + (size_t)row * KVW + hoff) =
                            __floats2half2_rn(v0, v1);
                        continue;
                    }
                }
                size_t o = (size_t)row * Mtot + col;
                if (add1) {
                    float2 a = __half22float2(*(const __half2*)(add1 + o));
                    v0 += a.x; v1 += a.y;
                }
                if (do_relu) { v0 = fmaxf(v0, 0.f); v1 = fmaxf(v1, 0.f); }
                if (C)    *(float2*)(C + o) = make_float2(v0, v1);
                if (Cmir) *(__half2*)(Cmir + o) = __floats2half2_rn(v0, v1);
            }
        }
    }
}

// ---------------------------------------------------------------------------
// Weight (fp16) + bias (fp32) packing + x fp16 convert, one kernel
// ---------------------------------------------------------------------------
__global__ void pack_wb(const float* __restrict__ w0,
                        const float* __restrict__ w1,
                        const float* __restrict__ w2,
                        const float* __restrict__ w3,
                        const float* __restrict__ w4,
                        const float* __restrict__ b1, const float* __restrict__ b2,
                        const float* __restrict__ b3, const float* __restrict__ b4,
                        const float* __restrict__ x,
                        __half* __restrict__ Wp, float* __restrict__ bp,
                        __half* __restrict__ x16)
{
    int idx = blockIdx.x * blockDim.x + threadIdx.x;
    const int NW4 = HID * MPK / 4;
    const int NX4 = NN * HID / 4;
    if (idx < NW4) {
        int row = idx / (MPK / 4);
        int col = (idx % (MPK / 4)) * 4;
        int b   = col >> 9;
        int c   = col & 511;
        const float* srcs[5] = {w0, w1, w2, w3, w4};
        float4 v = *(const float4*)(srcs[b] + (size_t)row * HC + c);
        __half2 h0 = __floats2half2_rn(v.x, v.y);
        __half2 h1 = __floats2half2_rn(v.z, v.w);
        *(uint2*)(Wp + (size_t)row * MPK + col) =
            make_uint2(*(unsigned*)&h0, *(unsigned*)&h1);
    } else if (idx < NW4 + MPK) {
        int col = idx - NW4;
        int b = col >> 9, c = col & 511;
        float v = 0.f;
        if (b == 1) v = b1[c];
        else if (b == 2) v = b2[c];
        else if (b == 3) v = b3[c];
        else if (b == 4) v = b4[c];
        bp[col] = v;
    } else if (idx < NW4 + MPK + NX4) {
        int i = idx - NW4 - MPK;
        float4 v = *(const float4*)(x + (size_t)i * 4);
        __half2 h0 = __floats2half2_rn(v.x, v.y);
        __half2 h1 = __floats2half2_rn(v.z, v.w);
        *(uint2*)(x16 + (size_t)i * 4) =
            make_uint2(*(unsigned*)&h0, *(unsigned*)&h1);
    }
}

// ---------------------------------------------------------------------------
// CSR build (by dst)
// ---------------------------------------------------------------------------
__global__ void deg_count(const int* __restrict__ dst, int* __restrict__ deg)
{
    int e = blockIdx.x * blockDim.x + threadIdx.x;
    if (e < EE) atomicAdd(&deg[dst[e]], 1);
}

__global__ void scan_offsets(const int* __restrict__ deg,
                             int* __restrict__ off, int* __restrict__ cur)
{
    extern __shared__ int sdeg[];
    __shared__ int wsum[32];
    const int t    = threadIdx.x;
    const int lane = t & 31;
    const int wid  = t >> 5;
    const int CH   = (NN + 1023) / 1024;

    for (int i = t; i < NN; i += 1024) sdeg[i] = deg[i];
    __syncthreads();

    int base = t * CH;
    int s = 0;
#pragma unroll
    for (int i = 0; i < CH; i++) {
        int idx = base + i;
        if (idx < NN) s += sdeg[idx];
    }
    int v = s;
#pragma unroll
    for (int o = 1; o < 32; o <<= 1) {
        int u = __shfl_up_sync(0xffffffffu, v, o);
        if (lane >= o) v += u;
    }
    if (lane == 31) wsum[wid] = v;
    __syncthreads();
    if (wid == 0) {
        int w = wsum[lane];
#pragma unroll
        for (int o = 1; o < 32; o <<= 1) {
            int u = __shfl_up_sync(0xffffffffu, w, o);
            if (lane >= o) w += u;
        }
        wsum[lane] = w;
    }
    __syncthreads();
    int excl = v - s + (wid ? wsum[wid - 1] : 0);
#pragma unroll
    for (int i = 0; i < CH; i++) {
        int idx = base + i;
        if (idx < NN) {
            off[idx] = excl;
            cur[idx] = excl;
            excl += sdeg[idx];
        }
    }
    if (t == 1023) off[NN] = excl;
}

__global__ void build_srcs(const int* __restrict__ src, const int* __restrict__ dst,
                           int* __restrict__ cur, int* __restrict__ srcs)
{
    int e = blockIdx.x * blockDim.x + threadIdx.x;
    if (e >= EE) return;
    int pos = atomicAdd(&cur[dst[e]], 1);
    srcs[pos] = src[e];
}

// ---------------------------------------------------------------------------
// GraphConv aggregation via CSR (fp16 gather, fp32 accumulate, fp16 store)
// ---------------------------------------------------------------------------
__global__ void gconv_agg(const __half* __restrict__ in,
                          const int* __restrict__ off,
                          const int* __restrict__ srcs,
                          __half* __restrict__ agg)
{
    int d = blockIdx.x;
    int c = threadIdx.x;
    int e0 = off[d], e1 = off[d + 1];
    float s = 0.f;
    int i = e0;
    for (; i + 3 < e1; i += 4) {
        int s0 = srcs[i], s1 = srcs[i + 1], s2 = srcs[i + 2], s3 = srcs[i + 3];
        s += __half2float(in[(size_t)s0 * HID + c])
           + __half2float(in[(size_t)s1 * HID + c])
           + __half2float(in[(size_t)s2 * HID + c])
           + __half2float(in[(size_t)s3 * HID + c]);
    }
    for (; i < e1; ++i)
        s += __half2float(in[(size_t)srcs[i] * HID + c]);
    agg[(size_t)d * HID + c] = __float2half_rn(s);
}

// ---------------------------------------------------------------------------
// Attention + transformer epilogue fused, 8 warps/node (2 warps per head).
// q/k/v gathered from compact fp16 kvq; ts/skip from fp32 pack; h2 out fp16.
// ---------------------------------------------------------------------------
__device__ __forceinline__ float4 ld_half4(const __half* p) {
    uint2 u = *(const uint2*)p;
    float2 fa = __half22float2(*(__half2*)&u.x);
    float2 fb = __half22float2(*(__half2*)&u.y);
    return make_float4(fa.x, fa.y, fb.x, fb.y);
}

__global__ void __launch_bounds__(256)
attn_fused(const float* __restrict__ pack,
           const __half* __restrict__ kvq,
           const int* __restrict__ off,
           const int* __restrict__ srcs,
           __half* __restrict__ h2)
{
    __shared__ float s_m[4], s_den[4], s_acc[4][128];

    int d    = blockIdx.x;
    int w    = threadIdx.x >> 5;
    int lane = threadIdx.x & 31;
    int h    = w & 3;
    int half = w >> 2;
    int e0 = off[d], e1 = off[d + 1];
    int emid = (e0 + e1) >> 1;
    int lo = half ? emid : e0;
    int hi = half ? e1   : emid;

    const int kvbase = 512 + h * 256;

    float4 qv = ld_half4(kvq + (size_t)d * KVW + h * HID + lane * 4);
    float4 acc = make_float4(0.f, 0.f, 0.f, 0.f);
    float mrun = NEGBIG, den = 0.f;

    int i = lo;
    for (; i + 1 < hi; i += 2) {
        int s0 = srcs[i], s1 = srcs[i + 1];
        const __half* p0 = kvq + (size_t)s0 * KVW + kvbase + lane * 4;
        const __half* p1 = kvq + (size_t)s1 * KVW + kvbase + lane * 4;
        float4 k0 = ld_half4(p0);
        float4 k1 = ld_half4(p1);
        float4 v0 = ld_half4(p0 + 128);
        float4 v1 = ld_half4(p1 + 128);
        float d0 = qv.x * k0.x + qv.y * k0.y + qv.z * k0.z + qv.w * k0.w;
        float d1 = qv.x * k1.x + qv.y * k1.y + qv.z * k1.z + qv.w * k1.w;
#pragma unroll
        for (int o = 16; o; o >>= 1) {
            d0 += __shfl_xor_sync(0xffffffffu, d0, o);
            d1 += __shfl_xor_sync(0xffffffffu, d1, o);
        }
        d0 *= 0.08838834764831843f;
        d1 *= 0.08838834764831843f;

        float mnew = fmaxf(mrun, d0);
        float corr = __expf(mrun - mnew);
        float wt   = __expf(d0 - mnew);
        den = den * corr + wt;
        acc.x = acc.x * corr + wt * v0.x;
        acc.y = acc.y * corr + wt * v0.y;
        acc.z = acc.z * corr + wt * v0.z;
        acc.w = acc.w * corr + wt * v0.w;
        mrun = mnew;

        mnew = fmaxf(mrun, d1);
        corr = __expf(mrun - mnew);
        wt   = __expf(d1 - mnew);
        den = den * corr + wt;
        acc.x = acc.x * corr + wt * v1.x;
        acc.y = acc.y * corr + wt * v1.y;
        acc.z = acc.z * corr + wt * v1.z;
        acc.w = acc.w * corr + wt * v1.w;
        mrun = mnew;
    }
    if (i < hi) {
        int s0 = srcs[i];
        const __half* p0 = kvq + (size_t)s0 * KVW + kvbase + lane * 4;
        float4 k0 = ld_half4(p0);
        float4 v0 = ld_half4(p0 + 128);
        float d0 = qv.x * k0.x + qv.y * k0.y + qv.z * k0.z + qv.w * k0.w;
#pragma unroll
        for (int o = 16; o; o >>= 1) d0 += __shfl_xor_sync(0xffffffffu, d0, o);
        d0 *= 0.08838834764831843f;
        float mnew = fmaxf(mrun, d0);
        float corr = __expf(mrun - mnew);
        float wt   = __expf(d0 - mnew);
        den = den * corr + wt;
        acc.x = acc.x * corr + wt * v0.x;
        acc.y = acc.y * corr + wt * v0.y;
        acc.z = acc.z * corr + wt * v0.z;
        acc.w = acc.w * corr + wt * v0.w;
        mrun = mnew;
    }

    if (half == 1) {
        if (lane == 0) { s_m[h] = mrun; s_den[h] = den; }
        *((float4*)&s_acc[h][0] + lane) = acc;
    }
    __syncthreads();
    if (half == 0) {
        float m1 = s_m[h], den1 = s_den[h];
        float4 a1 = *((const float4*)&s_acc[h][0] + lane);
        float mnew = fmaxf(mrun, m1);
        float c0 = __expf(mrun - mnew);
        float c1 = __expf(m1 - mnew);
        den = den * c0 + den1 * c1;
        acc.x = acc.x * c0 + a1.x * c1;
        acc.y = acc.y * c0 + a1.y * c1;
        acc.z = acc.z * c0 + a1.z * c1;
        acc.w = acc.w * c0 + a1.w * c1;

        float inv = 1.f / (den + 1e-16f);
        float4 ts = *((const float4*)(pack + 2048 + (size_t)d * MPK + h * HID) + lane);
        float4 sk = *((const float4*)(pack + 0    + (size_t)d * MPK + h * HID) + lane);
        float r0 = fmaxf(acc.x * inv + ts.x + sk.x, 0.f);
        float r1 = fmaxf(acc.y * inv + ts.y + sk.y, 0.f);
        float r2 = fmaxf(acc.z * inv + ts.z + sk.z, 0.f);
        float r3 = fmaxf(acc.w * inv + ts.w + sk.w, 0.f);
        __half2 q0 = __floats2half2_rn(r0, r1);
        __half2 q1 = __floats2half2_rn(r2, r3);
        *(uint2*)(h2 + (size_t)d * HC + h * HID + lane * 4) =
            make_uint2(*(unsigned*)&q0, *(unsigned*)&q1);
    }
}

// ---------------------------------------------------------------------------
// Pooling (fp16 input; batch sorted: accumulate runs, flush on group change)
// ---------------------------------------------------------------------------
#define PB 64
__global__ void pool_accum(const __half* __restrict__ h,
                           const int* __restrict__ batch,
                           float* __restrict__ pool, float* __restrict__ cnt)
{
    int c  = threadIdx.x;
    int n0 = blockIdx.x * PB;
    int n1 = min(n0 + PB, NN);
    float s = 0.f;
    int cb = batch[n0], count = 0;
    for (int n = n0; n < n1; ++n) {
        int b = batch[n];
        if (b != cb) {
            atomicAdd(&pool[cb * HID + c], s);
            if (c == 0) atomicAdd(&cnt[cb], (float)count);
            s = 0.f; count = 0; cb = b;
        }
        s += __half2float(h[(size_t)n * HID + c]);
        count++;
    }
    atomicAdd(&pool[cb * HID + c], s);
    if (c == 0) atomicAdd(&cnt[cb], (float)count);
}

__global__ void pool_fc(const float* __restrict__ pool,
                        const float* __restrict__ cnt,
                        const float* __restrict__ fcW,
                        const float* __restrict__ fcb,
                        float* __restrict__ out)
{
    int g = blockIdx.x;
    int c = threadIdx.x;
    float inv = 1.f / fmaxf(cnt[g], 1.f);
    float s = 0.f;
    for (int k = 0; k < HID; k++)
        s += pool[g * HID + k] * fcW[k * NCC + c];
    out[g * NCC + c] = s * inv + fcb[c];
}

// ---------------------------------------------------------------------------
// Launch
// ---------------------------------------------------------------------------
extern "C" void kernel_launch(void* const* d_in, const int* in_sizes, int n_in,
                              void* d_out, int out_size)
{
    const float* x        = (const float*)d_in[0];
    const int*   ei       = (const int*)  d_in[1];
    const int*   src      = ei;
    const int*   dst      = ei + EE;
    const int*   batch    = (const int*)  d_in[2];
    const float* c1_Wr    = (const float*)d_in[3];
    const float* c1_br    = (const float*)d_in[4];
    const float* c1_Wroot = (const float*)d_in[5];
    const float* tq_W  = (const float*)d_in[6];  const float* tq_b  = (const float*)d_in[7];
    const float* tk_W  = (const float*)d_in[8];  const float* tk_b  = (const float*)d_in[9];
    const float* tv_W  = (const float*)d_in[10]; const float* tv_b  = (const float*)d_in[11];
    const float* ts_W  = (const float*)d_in[12]; const float* ts_b  = (const float*)d_in[13];
    const float* skip_W = (const float*)d_in[14];
    const float* l1W    = (const float*)d_in[15]; const float* l1b = (const float*)d_in[16];
    const float* g1_Wr = (const float*)d_in[17]; const float* g1_br = (const float*)d_in[18];
    const float* g1_Wroot = (const float*)d_in[19];
    const float* g2_Wr = (const float*)d_in[20]; const float* g2_br = (const float*)d_in[21];
    const float* g2_Wroot = (const float*)d_in[22];
    const float* fc_W = (const float*)d_in[23]; const float* fc_b = (const float*)d_in[24];
    float* out = (float*)d_out;

    float *pack, *bpk, *pool, *cnt;
    __half *agg16, *x16, *h16, *h316, *h416, *h516, *h216, *kvq, *Wpk16;
    int *deg, *cur, *off, *srcs;
    cudaGetSymbolAddress((void**)&agg16, g_agg16);
    cudaGetSymbolAddress((void**)&x16,   g_x16);
    cudaGetSymbolAddress((void**)&h16,   g_h16);
    cudaGetSymbolAddress((void**)&h316,  g_h316);
    cudaGetSymbolAddress((void**)&h416,  g_h416);
    cudaGetSymbolAddress((void**)&h516,  g_h516);
    cudaGetSymbolAddress((void**)&h216,  g_h216);
    cudaGetSymbolAddress((void**)&pack,  g_pack);
    cudaGetSymbolAddress((void**)&kvq,   g_kvq);
    cudaGetSymbolAddress((void**)&Wpk16, g_Wpk16);
    cudaGetSymbolAddress((void**)&bpk,   g_bpk);
    cudaGetSymbolAddress((void**)&pool,  g_pool);
    cudaGetSymbolAddress((void**)&cnt,   g_cnt);
    cudaGetSymbolAddress((void**)&deg,   g_deg);
    cudaGetSymbolAddress((void**)&cur,   g_cur);
    cudaGetSymbolAddress((void**)&off,   g_off);
    cudaGetSymbolAddress((void**)&srcs,  g_srcs);

    const int SCAN_SMEM = NN * (int)sizeof(int);
    cudaFuncSetAttribute(scan_offsets, cudaFuncAttributeMaxDynamicSharedMemorySize,
                         SCAN_SMEM);

    const dim3 gb(256);
    const dim3 gridM128(NN / BM, 2);          // (125, 2): one wave
    const dim3 gridPK (NN / BM, MPK / 64);    // (125, 40)

    // --- weight+bias packing + x fp16 convert (one launch)
    const int PACK_THREADS = HID * MPK / 4 + MPK + NN * HID / 4;
    pack_wb<<<(PACK_THREADS + 255) / 256, 256>>>(
        skip_W, tq_W, tk_W, tv_W, ts_W, tq_b, tk_b, tv_b, ts_b, x,
        Wpk16, bpk, x16);

    // --- CSR build (by dst)
    cudaMemsetAsync(deg, 0, NN * sizeof(int));
    deg_count<<<(EE + 255) / 256, 256>>>(dst, deg);
    scan_offsets<<<1, 1024, SCAN_SMEM>>>(deg, off, cur);
    build_srcs<<<(EE + 255) / 256, 256>>>(src, dst, cur, srcs);

    // --- conv1: h16 = relu( (agg x) @ Wr + br + x @ Wroot )
    gconv_agg<<<NN, 128>>>(x16, off, srcs, agg16);
    gemm_mma<0><<<gridM128, gb>>>(agg16, c1_Wr, x16, c1_Wroot, c1_br,
                                  nullptr, nullptr, nullptr, h16,
                                  128, 128, 1);

    // --- packed projections: skip/ts -> fp32 pack, q/k/v -> fp16 kvq
    gemm_mma<1><<<gridPK, gb>>>(h16, Wpk16, nullptr, nullptr, bpk,
                                nullptr, pack, kvq, nullptr,
                                128, MPK, 0);

    // --- attention + fused epilogue -> h2 (fp16)
    attn_fused<<<NN, 256>>>(pack, kvq, off, srcs, h216);

    // --- h3 = relu(h2 @ lin1_W + lin1_b)
    gemm_mma<0><<<gridM128, gb>>>(h216, l1W, nullptr, nullptr, l1b,
                                  nullptr, nullptr, nullptr, h316,
                                  512, 128, 1);

    // --- gconv l1 with residual
    gconv_agg<<<NN, 128>>>(h316, off, srcs, agg16);
    gemm_mma<0><<<gridM128, gb>>>(agg16, g1_Wr, h316, g1_Wroot, g1_br,
                                  h316, nullptr, nullptr, h416,
                                  128, 128, 1);

    // --- gconv l2 with residual
    gconv_agg<<<NN, 128>>>(h416, off, srcs, agg16);
    gemm_mma<0><<<gridM128, gb>>>(agg16, g2_Wr, h416, g2_Wroot, g2_br,
                                  h416, nullptr, nullptr, h516,
                                  128, 128, 1);

    // --- mean pool + fc
    cudaMemsetAsync(pool, 0, (size_t)GG * HID * sizeof(float));
    cudaMemsetAsync(cnt,  0, (size_t)GG * sizeof(float));
    pool_accum<<<(NN + PB - 1) / PB, 128>>>(h516, batch, pool, cnt);
    pool_fc<<<GG, NCC>>>(pool, cnt, fc_W, fc_b, out);
}